// round 15
// baseline (speedup 1.0000x reference)
#include <cuda_runtime.h>
#include <cuda_bf16.h>
#include <math.h>
#include <stdint.h>

// Problem constants
#define BATCH 16
#define DIM 256
#define NHEADS 8
#define HEAD_DIM 32
#define KEY_DIM 16
#define NTOK 1024            // 32*32
#define QKV_OUT 512
#define BN_EPS 1e-3f
#define SCALE_F 0.25f        // KEY_DIM^-0.5
#define LOG2E 1.4426950408889634f

// Device scratch (allocation-free rule: static __device__ arrays)
__device__ float g_qkv[BATCH * QKV_OUT * NTOK];            // q(scaled tf32), k(tf32), v(fp32)
__device__ uint32_t g_vbf[BATCH * NHEADS * 32 * (NTOK/2)]; // v bf16x2 packed
__device__ float g_vattn[BATCH * DIM * NTOK];              // tf32-rounded
__device__ float g_xr[BATCH * DIM * NTOK];                 // tf32-rounded x
__device__ float g_wq[QKV_OUT * DIM];                      // tf32-rounded qkv_w
__device__ float g_wp[DIM * DIM];                          // tf32-rounded proj_w

// ---------------------------------------------------------------------------
// helpers
// ---------------------------------------------------------------------------
__device__ __forceinline__ float tf32r(float x) {
    uint32_t u;
    asm("cvt.rna.tf32.f32 %0, %1;" : "=r"(u) : "f"(x));
    return __uint_as_float(u);
}
__device__ __forceinline__ uint32_t pk2(float lo, float hi) {
    uint32_t r;  // lower half <- second source
    asm("cvt.rn.bf16x2.f32 %0, %1, %2;" : "=r"(r) : "f"(hi), "f"(lo));
    return r;
}
__device__ __forceinline__ float fex2(float x) {
    float y;
    asm("ex2.approx.ftz.f32 %0, %1;" : "=f"(y) : "f"(x));
    return y;
}
__device__ __forceinline__ void mma_tf32(
    float& d0, float& d1, float& d2, float& d3,
    uint32_t a0, uint32_t a1, uint32_t a2, uint32_t a3,
    uint32_t b0, uint32_t b1)
{
    asm volatile(
        "mma.sync.aligned.m16n8k8.row.col.f32.tf32.tf32.f32 "
        "{%0,%1,%2,%3}, {%4,%5,%6,%7}, {%8,%9}, {%0,%1,%2,%3};"
        : "+f"(d0), "+f"(d1), "+f"(d2), "+f"(d3)
        : "r"(a0), "r"(a1), "r"(a2), "r"(a3), "r"(b0), "r"(b1));
}
__device__ __forceinline__ void mma_bf16(
    float& d0, float& d1, float& d2, float& d3,
    uint32_t a0, uint32_t a1, uint32_t a2, uint32_t a3,
    uint32_t b0, uint32_t b1)
{
    asm volatile(
        "mma.sync.aligned.m16n8k16.row.col.f32.bf16.bf16.f32 "
        "{%0,%1,%2,%3}, {%4,%5,%6,%7}, {%8,%9}, {%0,%1,%2,%3};"
        : "+f"(d0), "+f"(d1), "+f"(d2), "+f"(d3)
        : "r"(a0), "r"(a1), "r"(a2), "r"(a3), "r"(b0), "r"(b1));
}
#define CP16(dst_u32, src_ptr) \
    asm volatile("cp.async.cg.shared.global [%0], [%1], 16;" \
                 :: "r"(dst_u32), "l"(src_ptr))

// ---------------------------------------------------------------------------
// K0: prep — tf32-round x, qkv_w, proj_w into scratch (L2-resident, ~5us).
// ---------------------------------------------------------------------------
__global__ __launch_bounds__(256) void prep_kernel(
    const float* __restrict__ x, const float* __restrict__ qw,
    const float* __restrict__ pw)
{
    const int NX = BATCH * DIM * NTOK / 4;
    const int NQ = QKV_OUT * DIM / 4;
    const int NP = DIM * DIM / 4;
    int idx = blockIdx.x * 256 + threadIdx.x;
    int stride = gridDim.x * 256;
    for (int i = idx; i < NX + NQ + NP; i += stride) {
        const float4* src; float4* dst; int j;
        if (i < NX)            { src = (const float4*)x;  dst = (float4*)g_xr; j = i; }
        else if (i < NX + NQ)  { src = (const float4*)qw; dst = (float4*)g_wq; j = i - NX; }
        else                   { src = (const float4*)pw; dst = (float4*)g_wp; j = i - NX - NQ; }
        float4 t = src[j];
        t.x = tf32r(t.x); t.y = tf32r(t.y); t.z = tf32r(t.z); t.w = tf32r(t.w);
        dst[j] = t;
    }
}

// ---------------------------------------------------------------------------
// K1/K4: tf32 tensor-core GEMM + BN (unchanged from rounds 12-14).
// ---------------------------------------------------------------------------
#define GASTR 20            // A row stride
#define GBSTR 132           // B row stride
#define G_BOFF (128 * GASTR)                 // 2560 floats
#define G_STG  (G_BOFF + 16 * GBSTR)         // 4672 floats per stage
#define G_NSTG 4
#define G_SMEM_BYTES (G_NSTG * G_STG * 4)    // 74752 B

__global__ __launch_bounds__(512, 2) void gemm_bn_tc(
    const float* __restrict__ X, const float* __restrict__ W,
    const float* __restrict__ gam, const float* __restrict__ bet,
    const float* __restrict__ mu, const float* __restrict__ va,
    float* __restrict__ out, uint32_t* __restrict__ vbf, int M)
{
    extern __shared__ float sm[];

    int b  = blockIdx.z;
    int o0 = blockIdx.y * 128;
    int n0 = blockIdx.x * 128;

    int tid = threadIdx.x, warp = tid >> 5, lane = tid & 31;
    int qr = lane >> 2, qc = lane & 3;
    int wm = (warp >> 2) * 32, wn = (warp & 3) * 32;

    const float* Xb = X + (size_t)b * 256 * NTOK;

    float C[2][4][4];
    #pragma unroll
    for (int i = 0; i < 2; i++)
        #pragma unroll
        for (int j = 0; j < 4; j++)
            #pragma unroll
            for (int r = 0; r < 4; r++) C[i][j][r] = 0.f;

    int arow = tid >> 2, acol = (tid & 3) * 4;     // A: 128 x 16
    int bkr  = tid >> 5, bnc  = (tid & 31) * 4;    // B: 16 x 128

    uint32_t smem_u32 = (uint32_t)__cvta_generic_to_shared(sm);
    uint32_t a_dst0 = smem_u32 + (arow * GASTR + acol) * 4;
    uint32_t b_dst0 = smem_u32 + (G_BOFF + bkr * GBSTR + bnc) * 4;
    const float* a_src0 = W + (o0 + arow) * 256 + acol;
    const float* b_src0 = Xb + bkr * NTOK + n0 + bnc;

    #pragma unroll
    for (int p = 0; p < 3; p++) {
        CP16(a_dst0 + p * G_STG * 4, a_src0 + p * 16);
        CP16(b_dst0 + p * G_STG * 4, b_src0 + (size_t)p * 16 * NTOK);
        asm volatile("cp.async.commit_group;");
    }

    for (int kc = 0; kc < 16; kc++) {
        asm volatile("cp.async.wait_group 2;");
        __syncthreads();

        if (kc + 3 < 16) {
            int buf = (kc + 3) & 3;
            CP16(a_dst0 + buf * G_STG * 4, a_src0 + (kc + 3) * 16);
            CP16(b_dst0 + buf * G_STG * 4, b_src0 + (size_t)(kc + 3) * 16 * NTOK);
        }
        asm volatile("cp.async.commit_group;");

        const float* Ab = sm + (kc & 3) * G_STG;
        const float* Bb = Ab + G_BOFF;

        #pragma unroll
        for (int ks = 0; ks < 2; ks++) {
            int kk = ks * 8;
            uint32_t af[2][4];
            #pragma unroll
            for (int mt = 0; mt < 2; mt++) {
                int r = wm + mt * 16 + qr;
                af[mt][0] = __float_as_uint(Ab[r * GASTR + kk + qc]);
                af[mt][1] = __float_as_uint(Ab[(r + 8) * GASTR + kk + qc]);
                af[mt][2] = __float_as_uint(Ab[r * GASTR + kk + qc + 4]);
                af[mt][3] = __float_as_uint(Ab[(r + 8) * GASTR + kk + qc + 4]);
            }
            uint32_t bfr[4][2];
            #pragma unroll
            for (int nt = 0; nt < 4; nt++) {
                bfr[nt][0] = __float_as_uint(Bb[(kk + qc) * GBSTR + wn + nt * 8 + qr]);
                bfr[nt][1] = __float_as_uint(Bb[(kk + qc + 4) * GBSTR + wn + nt * 8 + qr]);
            }
            #pragma unroll
            for (int mt = 0; mt < 2; mt++)
                #pragma unroll
                for (int nt = 0; nt < 4; nt++)
                    mma_tf32(C[mt][nt][0], C[mt][nt][1], C[mt][nt][2], C[mt][nt][3],
                             af[mt][0], af[mt][1], af[mt][2], af[mt][3],
                             bfr[nt][0], bfr[nt][1]);
        }
    }

    const float qsc = SCALE_F * LOG2E;
    bool fmt = (M == QKV_OUT);
    #pragma unroll
    for (int mt = 0; mt < 2; mt++) {
        int r_lo = o0 + wm + mt * 16 + qr;
        int r_hi = r_lo + 8;
        float inv0 = gam[r_lo] * rsqrtf(va[r_lo] + BN_EPS);
        float sh0  = bet[r_lo] - mu[r_lo] * inv0;
        float inv1 = gam[r_hi] * rsqrtf(va[r_hi] + BN_EPS);
        float sh1  = bet[r_hi] - mu[r_hi] * inv1;
        int band = (r_lo & 63) >> 4;
        #pragma unroll
        for (int nt = 0; nt < 4; nt++) {
            int col = n0 + wn + nt * 8 + 2 * qc;
            float w0 = C[mt][nt][0] * inv0 + sh0;
            float w1 = C[mt][nt][1] * inv0 + sh0;
            float w2 = C[mt][nt][2] * inv1 + sh1;
            float w3 = C[mt][nt][3] * inv1 + sh1;
            if (fmt) {
                if (band == 0) {
                    w0 = tf32r(w0 * qsc); w1 = tf32r(w1 * qsc);
                    w2 = tf32r(w2 * qsc); w3 = tf32r(w3 * qsc);
                } else if (band == 1) {
                    w0 = tf32r(w0); w1 = tf32r(w1);
                    w2 = tf32r(w2); w3 = tf32r(w3);
                } else {
                    int hh0 = r_lo >> 6, dd0 = (r_lo & 63) - 32;
                    int hh1 = r_hi >> 6, dd1 = (r_hi & 63) - 32;
                    vbf[((size_t)(b * NHEADS + hh0) * 32 + dd0) * (NTOK/2) + (col >> 1)] = pk2(w0, w1);
                    vbf[((size_t)(b * NHEADS + hh1) * 32 + dd1) * (NTOK/2) + (col >> 1)] = pk2(w2, w3);
                }
            }
            *(float2*)&out[((size_t)b * M + r_lo) * NTOK + col] = make_float2(w0, w1);
            *(float2*)&out[((size_t)b * M + r_hi) * NTOK + col] = make_float2(w2, w3);
        }
    }
}

// ---------------------------------------------------------------------------
// K2: flash attention, max-free softmax, KEY-SPLIT warps:
//   wg = warp>>2 owns a 32-key half of each 64-key tile,
//   wi = warp&3 owns 32 q-rows (2 m-frags).
// B-fragments amortize over 2 mmas -> CTA smem crossbar traffic halved.
// Partial O / row-sums merge by simple addition at the end (no rescale
// needed thanks to max-free softmax). 3-stage cp.async ring. 2 CTAs/SM.
// ---------------------------------------------------------------------------
#define QSTR 21
#define KSTR2 72            // K row stride (floats)
#define VSTR2 36            // V row stride (words)
#define KBUF2 (16 * KSTR2)  // 1152 floats
#define VBUF2 (32 * VSTR2)  // 1152 words
#define BUFSZ2 (KBUF2 + VBUF2)       // 2304 floats per stage
#define S_TOTAL2 11488               // main loop: 2688 + 3*2304 = 9600 < 11488

__global__ __launch_bounds__(256, 2) void attn_kernel(
    const float* __restrict__ qkv, const uint32_t* __restrict__ vbf,
    float* __restrict__ vattn,
    const float* __restrict__ pe_w,
    const float* __restrict__ pe_g, const float* __restrict__ pe_b,
    const float* __restrict__ pe_m, const float* __restrict__ pe_v)
{
    __shared__ __align__(16) float s_all[S_TOTAL2];
    float* s_q   = s_all;
    float* s_buf = s_all + 128 * QSTR;

    int tid  = threadIdx.x;
    int b    = blockIdx.z, h = blockIdx.y;
    int m0   = blockIdx.x * 128;

    int warp = tid >> 5, lane = tid & 31;
    int qr = lane >> 2;
    int qc = lane & 3;
    int wg = warp >> 2;            // key-half (0/1)
    int wi = warp & 3;             // m-quarter (32 rows)
    int mwb = wi * 32;             // warp's m base
    int nb  = wg * 32;             // warp's key base within tile

    const float* base = qkv + ((size_t)b * QKV_OUT + h * 64) * NTOK;
    const uint32_t* vbase = vbf + (size_t)(b * NHEADS + h) * 32 * (NTOK/2);

    uint32_t sbuf_u32 = (uint32_t)__cvta_generic_to_shared(s_buf);
    int kd = tid >> 4, kc4 = (tid & 15) * 4;
    int vd = tid >> 3, vc4 = (tid & 7) * 4;
    uint32_t k_dst0 = sbuf_u32 + (kd * KSTR2 + kc4) * 4;
    uint32_t v_dst0 = sbuf_u32 + (KBUF2 + vd * VSTR2 + vc4) * 4;
    const float*    k_src0 = base + (16 + kd) * NTOK + kc4;
    const uint32_t* v_src0 = vbase + vd * (NTOK/2) + vc4;

    // q tile (pre-scaled tf32 written by K1): plain copy
    for (int i = tid; i < 16 * 128; i += 256) {
        int d = i >> 7, mm = i & 127;
        s_q[mm * QSTR + d] = base[d * NTOK + m0 + mm];
    }
    __syncthreads();

    // A-frags for 2 m-frags
    uint32_t aq[2][2][4];
    #pragma unroll
    for (int mf = 0; mf < 2; mf++) {
        int r = mwb + mf * 16 + qr;
        #pragma unroll
        for (int kk = 0; kk < 2; kk++) {
            aq[mf][kk][0] = __float_as_uint(s_q[r       * QSTR + kk * 8 + qc]);
            aq[mf][kk][1] = __float_as_uint(s_q[(r + 8) * QSTR + kk * 8 + qc]);
            aq[mf][kk][2] = __float_as_uint(s_q[r       * QSTR + kk * 8 + qc + 4]);
            aq[mf][kk][3] = __float_as_uint(s_q[(r + 8) * QSTR + kk * 8 + qc + 4]);
        }
    }

    float rsum[2][2] = {{0.f, 0.f}, {0.f, 0.f}};   // [mf][row-half]
    float O[2][4][4];
    #pragma unroll
    for (int mf = 0; mf < 2; mf++)
        #pragma unroll
        for (int j = 0; j < 4; j++)
            #pragma unroll
            for (int r = 0; r < 4; r++) O[mf][j][r] = 0.f;

    // prologue: tiles 0,1 into stages 0,1 (depth-2 prefetch)
    #pragma unroll
    for (int p = 0; p < 2; p++) {
        uint32_t off = p * BUFSZ2 * 4;
        CP16(k_dst0 + off, k_src0 + p * 64);
        CP16(v_dst0 + off, v_src0 + p * 32);
        asm volatile("cp.async.commit_group;");
    }

    int st = 0, st2 = 2;
    for (int t = 0; t < 16; t++) {
        asm volatile("cp.async.wait_group 1;");
        __syncthreads();

        if (t + 2 < 16) {
            int n0 = (t + 2) * 64;
            uint32_t off = st2 * BUFSZ2 * 4;
            CP16(k_dst0 + off, k_src0 + n0);
            CP16(v_dst0 + off, v_src0 + (n0 >> 1));
        }
        asm volatile("cp.async.commit_group;");

        const float*    kf = s_buf + st * BUFSZ2;
        const uint32_t* vw = (const uint32_t*)(kf + KBUF2);

        // ---- QK (tf32): S[mf][nt][4], warp's 32-key half
        float S[2][4][4];
        #pragma unroll
        for (int mf = 0; mf < 2; mf++)
            #pragma unroll
            for (int nt = 0; nt < 4; nt++)
                #pragma unroll
                for (int r = 0; r < 4; r++) S[mf][nt][r] = 0.f;
        #pragma unroll
        for (int nt = 0; nt < 4; nt++) {
            #pragma unroll
            for (int kk = 0; kk < 2; kk++) {
                uint32_t b0 = __float_as_uint(kf[(kk*8 + qc)     * KSTR2 + nb + nt*8 + qr]);
                uint32_t b1 = __float_as_uint(kf[(kk*8 + qc + 4) * KSTR2 + nb + nt*8 + qr]);
                #pragma unroll
                for (int mf = 0; mf < 2; mf++)
                    mma_tf32(S[mf][nt][0], S[mf][nt][1], S[mf][nt][2], S[mf][nt][3],
                             aq[mf][kk][0], aq[mf][kk][1], aq[mf][kk][2], aq[mf][kk][3],
                             b0, b1);
            }
        }

        // ---- raw exp2 (scores bounded), accumulate partial sums
        #pragma unroll
        for (int mf = 0; mf < 2; mf++) {
            float p0 = 0.f, p1 = 0.f;
            #pragma unroll
            for (int nt = 0; nt < 4; nt++) {
                float e0 = fex2(S[mf][nt][0]);
                float e1 = fex2(S[mf][nt][1]);
                float e2 = fex2(S[mf][nt][2]);
                float e3 = fex2(S[mf][nt][3]);
                S[mf][nt][0] = e0; S[mf][nt][1] = e1;
                S[mf][nt][2] = e2; S[mf][nt][3] = e3;
                p0 += e0 + e1; p1 += e2 + e3;
            }
            rsum[mf][0] += p0;
            rsum[mf][1] += p1;
        }

        // ---- PV (bf16): warp's 32 keys = 2 ksteps of 16
        #pragma unroll
        for (int ktl = 0; ktl < 2; ktl++) {
            uint32_t a[2][4];
            #pragma unroll
            for (int mf = 0; mf < 2; mf++) {
                a[mf][0] = pk2(S[mf][2*ktl][0],   S[mf][2*ktl][1]);
                a[mf][1] = pk2(S[mf][2*ktl][2],   S[mf][2*ktl][3]);
                a[mf][2] = pk2(S[mf][2*ktl+1][0], S[mf][2*ktl+1][1]);
                a[mf][3] = pk2(S[mf][2*ktl+1][2], S[mf][2*ktl+1][3]);
            }
            int kw = (wg * 2 + ktl) * 8;
            #pragma unroll
            for (int dt = 0; dt < 4; dt++) {
                uint32_t b0 = vw[(dt*8 + qr) * VSTR2 + kw + qc];
                uint32_t b1 = vw[(dt*8 + qr) * VSTR2 + kw + qc + 4];
                #pragma unroll
                for (int mf = 0; mf < 2; mf++)
                    mma_bf16(O[mf][dt][0], O[mf][dt][1], O[mf][dt][2], O[mf][dt][3],
                             a[mf][0], a[mf][1], a[mf][2], a[mf][3], b0, b1);
            }
        }

        st  = (st  == 2) ? 0 : st + 1;
        st2 = (st2 == 2) ? 0 : st2 + 1;
    }
    __syncthreads();

    // reduce rsum over qc lanes
    #pragma unroll
    for (int mf = 0; mf < 2; mf++)
        #pragma unroll
        for (int rh = 0; rh < 2; rh++) {
            rsum[mf][rh] += __shfl_xor_sync(0xffffffffu, rsum[mf][rh], 1);
            rsum[mf][rh] += __shfl_xor_sync(0xffffffffu, rsum[mf][rh], 2);
        }

    // epilogue smem overlay
    float* ob    = s_all;            // [128][33]   4224
    float* rsbuf = s_all + 4224;     // [2][128]    256
    float* pv    = s_all + 4480;     // [32][6][34] 6528
    float* pwb   = s_all + 11008;    // 288
    float* pinv  = s_all + 11296;    // 32
    float* psh   = s_all + 11328;    // 32
    float* rinv  = s_all + 11360;    // 128

    // phase A: wg0 writes raw O; both groups write their rsum half
    if (wg == 0) {
        #pragma unroll
        for (int mf = 0; mf < 2; mf++) {
            int r = mwb + mf * 16 + qr;
            #pragma unroll
            for (int dt = 0; dt < 4; dt++) {
                ob[r       * 33 + dt*8 + 2*qc]     = O[mf][dt][0];
                ob[r       * 33 + dt*8 + 2*qc + 1] = O[mf][dt][1];
                ob[(r + 8) * 33 + dt*8 + 2*qc]     = O[mf][dt][2];
                ob[(r + 8) * 33 + dt*8 + 2*qc + 1] = O[mf][dt][3];
            }
        }
    }
    if (qc == 0) {
        #pragma unroll
        for (int mf = 0; mf < 2; mf++) {
            int r = mwb + mf * 16 + qr;
            rsbuf[wg * 128 + r]     = rsum[mf][0];
            rsbuf[wg * 128 + r + 8] = rsum[mf][1];
        }
    }
    __syncthreads();

    // phase B: wg1 adds its O; first 128 threads compute 1/rs_total
    if (wg == 1) {
        #pragma unroll
        for (int mf = 0; mf < 2; mf++) {
            int r = mwb + mf * 16 + qr;
            #pragma unroll
            for (int dt = 0; dt < 4; dt++) {
                ob[r       * 33 + dt*8 + 2*qc]     += O[mf][dt][0];
                ob[r       * 33 + dt*8 + 2*qc + 1] += O[mf][dt][1];
                ob[(r + 8) * 33 + dt*8 + 2*qc]     += O[mf][dt][2];
                ob[(r + 8) * 33 + dt*8 + 2*qc + 1] += O[mf][dt][3];
            }
        }
    } else if (tid < 128) {
        rinv[tid] = 1.0f / (rsbuf[tid] + rsbuf[128 + tid]);
    }
    __syncthreads();

    // phase C: v halo + pe params
    {
        int r0 = blockIdx.x * 4;
        const float* vfp = base + 32 * NTOK;
        for (int i = tid; i < 32 * 6 * 34; i += 256) {
            int d  = i / 204;
            int rm = i % 204;
            int yy = rm / 34;
            int xx = rm % 34;
            int x  = xx - 1;
            int ry = r0 - 1 + yy;
            float val = 0.f;
            if ((unsigned)x < 32u && (unsigned)ry < 32u)
                val = vfp[d * NTOK + ry * 32 + x];
            pv[i] = val;
        }
        for (int i = tid; i < 288; i += 256)
            pwb[i] = pe_w[h * 32 * 9 + i];
        if (tid < 32) {
            int c = h * 32 + tid;
            float iv = pe_g[c] * rsqrtf(pe_v[c] + BN_EPS);
            pinv[tid] = iv;
            psh[tid]  = pe_b[c] - pe_m[c] * iv;
        }
    }
    __syncthreads();

    // out = tf32( v_attn + BN(dwconv3x3(v)) )
    float* outp = vattn + ((size_t)b * DIM + h * HEAD_DIM) * NTOK + m0;
    for (int i = tid; i < 32 * 128; i += 256) {
        int d = i >> 7, mm = i & 127;
        int y = mm >> 5, x = mm & 31;
        const float* wd = &pwb[d * 9];
        const float* p0 = &pv[d * 204 + y * 34 + x];
        float pe = wd[0]*p0[0]  + wd[1]*p0[1]  + wd[2]*p0[2]
                 + wd[3]*p0[34] + wd[4]*p0[35] + wd[5]*p0[36]
                 + wd[6]*p0[68] + wd[7]*p0[69] + wd[8]*p0[70];
        outp[d * NTOK + mm] = tf32r(ob[mm * 33 + d] * rinv[mm] + pe * pinv[d] + psh[d]);
    }
}

// ---------------------------------------------------------------------------
extern "C" void kernel_launch(void* const* d_in, const int* in_sizes, int n_in,
                              void* d_out, int out_size)
{
    const float* x        = (const float*)d_in[0];
    const float* qkv_w    = (const float*)d_in[1];
    const float* qkv_g    = (const float*)d_in[2];
    const float* qkv_b    = (const float*)d_in[3];
    const float* qkv_m    = (const float*)d_in[4];
    const float* qkv_v    = (const float*)d_in[5];
    const float* pe_w     = (const float*)d_in[6];
    const float* pe_g     = (const float*)d_in[7];
    const float* pe_b     = (const float*)d_in[8];
    const float* pe_m     = (const float*)d_in[9];
    const float* pe_v     = (const float*)d_in[10];
    const float* proj_w   = (const float*)d_in[11];
    const float* proj_g   = (const float*)d_in[12];
    const float* proj_b   = (const float*)d_in[13];
    const float* proj_m   = (const float*)d_in[14];
    const float* proj_v   = (const float*)d_in[15];
    float* out            = (float*)d_out;

    float *qkv_ptr, *vattn_ptr, *xr_ptr, *wq_ptr, *wp_ptr;
    uint32_t* vbf_ptr;
    cudaGetSymbolAddress((void**)&qkv_ptr, g_qkv);
    cudaGetSymbolAddress((void**)&vattn_ptr, g_vattn);
    cudaGetSymbolAddress((void**)&xr_ptr, g_xr);
    cudaGetSymbolAddress((void**)&wq_ptr, g_wq);
    cudaGetSymbolAddress((void**)&wp_ptr, g_wp);
    cudaGetSymbolAddress((void**)&vbf_ptr, g_vbf);

    cudaFuncSetAttribute(gemm_bn_tc,
        cudaFuncAttributeMaxDynamicSharedMemorySize, G_SMEM_BYTES);

    // K0: pre-round inputs to tf32
    prep_kernel<<<512, 256>>>(x, qkv_w, proj_w);

    // K1: qkv = BN(conv1x1(x)) + attn-operand formatting
    gemm_bn_tc<<<dim3(8, 4, BATCH), 512, G_SMEM_BYTES>>>(
        xr_ptr, wq_ptr, qkv_g, qkv_b, qkv_m, qkv_v, qkv_ptr, vbf_ptr, QKV_OUT);

    // K2: attention (key-split warps, max-free softmax) + fused pos-enc
    attn_kernel<<<dim3(8, NHEADS, BATCH), 256>>>(
        qkv_ptr, vbf_ptr, vattn_ptr, pe_w, pe_g, pe_b, pe_m, pe_v);

    // K4: out = BN(conv1x1(vattn))
    gemm_bn_tc<<<dim3(8, 2, BATCH), 512, G_SMEM_BYTES>>>(
        vattn_ptr, wp_ptr, proj_g, proj_b, proj_m, proj_v, out, vbf_ptr, DIM);
}

// round 17
// speedup vs baseline: 1.0238x; 1.0238x over previous
#include <cuda_runtime.h>
#include <cuda_bf16.h>
#include <math.h>
#include <stdint.h>

// Problem constants
#define BATCH 16
#define DIM 256
#define NHEADS 8
#define HEAD_DIM 32
#define KEY_DIM 16
#define NTOK 1024            // 32*32
#define QKV_OUT 512
#define BN_EPS 1e-3f
#define SCALE_F 0.25f        // KEY_DIM^-0.5
#define LOG2E 1.4426950408889634f

// Device scratch (allocation-free rule: static __device__ arrays)
__device__ float g_qkv[BATCH * QKV_OUT * NTOK];            // q(scaled tf32), k(tf32), v(fp32)
__device__ uint32_t g_vbf[BATCH * NHEADS * 32 * (NTOK/2)]; // v bf16x2 packed
__device__ float g_vattn[BATCH * DIM * NTOK];              // tf32-rounded
__device__ float g_xr[BATCH * DIM * NTOK];                 // tf32-rounded x
__device__ float g_wq[QKV_OUT * DIM];                      // tf32-rounded qkv_w
__device__ float g_wp[DIM * DIM];                          // tf32-rounded proj_w

// ---------------------------------------------------------------------------
// helpers
// ---------------------------------------------------------------------------
__device__ __forceinline__ float tf32r(float x) {
    uint32_t u;
    asm("cvt.rna.tf32.f32 %0, %1;" : "=r"(u) : "f"(x));
    return __uint_as_float(u);
}
__device__ __forceinline__ uint32_t pk2(float lo, float hi) {
    uint32_t r;  // lower half <- second source
    asm("cvt.rn.bf16x2.f32 %0, %1, %2;" : "=r"(r) : "f"(hi), "f"(lo));
    return r;
}
__device__ __forceinline__ float fex2(float x) {
    float y;
    asm("ex2.approx.ftz.f32 %0, %1;" : "=f"(y) : "f"(x));
    return y;
}
__device__ __forceinline__ void mma_tf32(
    float& d0, float& d1, float& d2, float& d3,
    uint32_t a0, uint32_t a1, uint32_t a2, uint32_t a3,
    uint32_t b0, uint32_t b1)
{
    asm volatile(
        "mma.sync.aligned.m16n8k8.row.col.f32.tf32.tf32.f32 "
        "{%0,%1,%2,%3}, {%4,%5,%6,%7}, {%8,%9}, {%0,%1,%2,%3};"
        : "+f"(d0), "+f"(d1), "+f"(d2), "+f"(d3)
        : "r"(a0), "r"(a1), "r"(a2), "r"(a3), "r"(b0), "r"(b1));
}
__device__ __forceinline__ void mma_bf16(
    float& d0, float& d1, float& d2, float& d3,
    uint32_t a0, uint32_t a1, uint32_t a2, uint32_t a3,
    uint32_t b0, uint32_t b1)
{
    asm volatile(
        "mma.sync.aligned.m16n8k16.row.col.f32.bf16.bf16.f32 "
        "{%0,%1,%2,%3}, {%4,%5,%6,%7}, {%8,%9}, {%0,%1,%2,%3};"
        : "+f"(d0), "+f"(d1), "+f"(d2), "+f"(d3)
        : "r"(a0), "r"(a1), "r"(a2), "r"(a3), "r"(b0), "r"(b1));
}
#define CP16(dst_u32, src_ptr) \
    asm volatile("cp.async.cg.shared.global [%0], [%1], 16;" \
                 :: "r"(dst_u32), "l"(src_ptr))

// ---------------------------------------------------------------------------
// K0: prep — tf32-round x, qkv_w, proj_w into scratch (L2-resident, ~5us).
// ---------------------------------------------------------------------------
__global__ __launch_bounds__(256) void prep_kernel(
    const float* __restrict__ x, const float* __restrict__ qw,
    const float* __restrict__ pw)
{
    const int NX = BATCH * DIM * NTOK / 4;
    const int NQ = QKV_OUT * DIM / 4;
    const int NP = DIM * DIM / 4;
    int idx = blockIdx.x * 256 + threadIdx.x;
    int stride = gridDim.x * 256;
    for (int i = idx; i < NX + NQ + NP; i += stride) {
        const float4* src; float4* dst; int j;
        if (i < NX)            { src = (const float4*)x;  dst = (float4*)g_xr; j = i; }
        else if (i < NX + NQ)  { src = (const float4*)qw; dst = (float4*)g_wq; j = i - NX; }
        else                   { src = (const float4*)pw; dst = (float4*)g_wp; j = i - NX - NQ; }
        float4 t = src[j];
        t.x = tf32r(t.x); t.y = tf32r(t.y); t.z = tf32r(t.z); t.w = tf32r(t.w);
        dst[j] = t;
    }
}

// ---------------------------------------------------------------------------
// K1/K4: tf32 tensor-core GEMM + BN (R12/R13 proven config).
// ---------------------------------------------------------------------------
#define GASTR 20            // A row stride
#define GBSTR 132           // B row stride
#define G_BOFF (128 * GASTR)                 // 2560 floats
#define G_STG  (G_BOFF + 16 * GBSTR)         // 4672 floats per stage
#define G_NSTG 4
#define G_SMEM_BYTES (G_NSTG * G_STG * 4)    // 74752 B

__global__ __launch_bounds__(512, 2) void gemm_bn_tc(
    const float* __restrict__ X, const float* __restrict__ W,
    const float* __restrict__ gam, const float* __restrict__ bet,
    const float* __restrict__ mu, const float* __restrict__ va,
    float* __restrict__ out, uint32_t* __restrict__ vbf, int M)
{
    extern __shared__ float sm[];

    int b  = blockIdx.z;
    int o0 = blockIdx.y * 128;
    int n0 = blockIdx.x * 128;

    int tid = threadIdx.x, warp = tid >> 5, lane = tid & 31;
    int qr = lane >> 2, qc = lane & 3;
    int wm = (warp >> 2) * 32, wn = (warp & 3) * 32;

    const float* Xb = X + (size_t)b * 256 * NTOK;

    float C[2][4][4];
    #pragma unroll
    for (int i = 0; i < 2; i++)
        #pragma unroll
        for (int j = 0; j < 4; j++)
            #pragma unroll
            for (int r = 0; r < 4; r++) C[i][j][r] = 0.f;

    int arow = tid >> 2, acol = (tid & 3) * 4;     // A: 128 x 16
    int bkr  = tid >> 5, bnc  = (tid & 31) * 4;    // B: 16 x 128

    uint32_t smem_u32 = (uint32_t)__cvta_generic_to_shared(sm);
    uint32_t a_dst0 = smem_u32 + (arow * GASTR + acol) * 4;
    uint32_t b_dst0 = smem_u32 + (G_BOFF + bkr * GBSTR + bnc) * 4;
    const float* a_src0 = W + (o0 + arow) * 256 + acol;
    const float* b_src0 = Xb + bkr * NTOK + n0 + bnc;

    #pragma unroll
    for (int p = 0; p < 3; p++) {
        CP16(a_dst0 + p * G_STG * 4, a_src0 + p * 16);
        CP16(b_dst0 + p * G_STG * 4, b_src0 + (size_t)p * 16 * NTOK);
        asm volatile("cp.async.commit_group;");
    }

    for (int kc = 0; kc < 16; kc++) {
        asm volatile("cp.async.wait_group 2;");
        __syncthreads();

        if (kc + 3 < 16) {
            int buf = (kc + 3) & 3;
            CP16(a_dst0 + buf * G_STG * 4, a_src0 + (kc + 3) * 16);
            CP16(b_dst0 + buf * G_STG * 4, b_src0 + (size_t)(kc + 3) * 16 * NTOK);
        }
        asm volatile("cp.async.commit_group;");

        const float* Ab = sm + (kc & 3) * G_STG;
        const float* Bb = Ab + G_BOFF;

        #pragma unroll
        for (int ks = 0; ks < 2; ks++) {
            int kk = ks * 8;
            uint32_t af[2][4];
            #pragma unroll
            for (int mt = 0; mt < 2; mt++) {
                int r = wm + mt * 16 + qr;
                af[mt][0] = __float_as_uint(Ab[r * GASTR + kk + qc]);
                af[mt][1] = __float_as_uint(Ab[(r + 8) * GASTR + kk + qc]);
                af[mt][2] = __float_as_uint(Ab[r * GASTR + kk + qc + 4]);
                af[mt][3] = __float_as_uint(Ab[(r + 8) * GASTR + kk + qc + 4]);
            }
            uint32_t bfr[4][2];
            #pragma unroll
            for (int nt = 0; nt < 4; nt++) {
                bfr[nt][0] = __float_as_uint(Bb[(kk + qc) * GBSTR + wn + nt * 8 + qr]);
                bfr[nt][1] = __float_as_uint(Bb[(kk + qc + 4) * GBSTR + wn + nt * 8 + qr]);
            }
            #pragma unroll
            for (int mt = 0; mt < 2; mt++)
                #pragma unroll
                for (int nt = 0; nt < 4; nt++)
                    mma_tf32(C[mt][nt][0], C[mt][nt][1], C[mt][nt][2], C[mt][nt][3],
                             af[mt][0], af[mt][1], af[mt][2], af[mt][3],
                             bfr[nt][0], bfr[nt][1]);
        }
    }

    const float qsc = SCALE_F * LOG2E;
    bool fmt = (M == QKV_OUT);
    #pragma unroll
    for (int mt = 0; mt < 2; mt++) {
        int r_lo = o0 + wm + mt * 16 + qr;
        int r_hi = r_lo + 8;
        float inv0 = gam[r_lo] * rsqrtf(va[r_lo] + BN_EPS);
        float sh0  = bet[r_lo] - mu[r_lo] * inv0;
        float inv1 = gam[r_hi] * rsqrtf(va[r_hi] + BN_EPS);
        float sh1  = bet[r_hi] - mu[r_hi] * inv1;
        int band = (r_lo & 63) >> 4;
        #pragma unroll
        for (int nt = 0; nt < 4; nt++) {
            int col = n0 + wn + nt * 8 + 2 * qc;
            float w0 = C[mt][nt][0] * inv0 + sh0;
            float w1 = C[mt][nt][1] * inv0 + sh0;
            float w2 = C[mt][nt][2] * inv1 + sh1;
            float w3 = C[mt][nt][3] * inv1 + sh1;
            if (fmt) {
                if (band == 0) {
                    w0 = tf32r(w0 * qsc); w1 = tf32r(w1 * qsc);
                    w2 = tf32r(w2 * qsc); w3 = tf32r(w3 * qsc);
                } else if (band == 1) {
                    w0 = tf32r(w0); w1 = tf32r(w1);
                    w2 = tf32r(w2); w3 = tf32r(w3);
                } else {
                    int hh0 = r_lo >> 6, dd0 = (r_lo & 63) - 32;
                    int hh1 = r_hi >> 6, dd1 = (r_hi & 63) - 32;
                    vbf[((size_t)(b * NHEADS + hh0) * 32 + dd0) * (NTOK/2) + (col >> 1)] = pk2(w0, w1);
                    vbf[((size_t)(b * NHEADS + hh1) * 32 + dd1) * (NTOK/2) + (col >> 1)] = pk2(w2, w3);
                }
            }
            *(float2*)&out[((size_t)b * M + r_lo) * NTOK + col] = make_float2(w0, w1);
            *(float2*)&out[((size_t)b * M + r_hi) * NTOK + col] = make_float2(w2, w3);
        }
    }
}

// ---------------------------------------------------------------------------
// K2: flash attention (R13 config) with exp2 INTERLEAVED into the PV loop:
// per kt-pair, exp the 8 scores, pack, and immediately issue the 4 PV mmas —
// independent kt chains let MUFU bursts overlap tensor work in one warp.
// ---------------------------------------------------------------------------
#define QSTR 21
#define KSTR2 72            // K row stride (floats)
#define VSTR2 36            // V row stride (words)
#define KBUF2 (16 * KSTR2)  // 1152 floats
#define VBUF2 (32 * VSTR2)  // 1152 words
#define BUFSZ2 (KBUF2 + VBUF2)
#define S_TOTAL2 11104

__global__ __launch_bounds__(256, 3) void attn_kernel(
    const float* __restrict__ qkv, const uint32_t* __restrict__ vbf,
    float* __restrict__ vattn,
    const float* __restrict__ pe_w,
    const float* __restrict__ pe_g, const float* __restrict__ pe_b,
    const float* __restrict__ pe_m, const float* __restrict__ pe_v)
{
    __shared__ __align__(16) float s_all[S_TOTAL2];
    float* s_q   = s_all;
    float* s_buf = s_all + 128 * QSTR;

    int tid  = threadIdx.x;
    int b    = blockIdx.z, h = blockIdx.y;
    int m0   = blockIdx.x * 128;

    int warp = tid >> 5, lane = tid & 31;
    int qr = lane >> 2;
    int qc = lane & 3;
    int mw = warp * 16;

    const float* base = qkv + ((size_t)b * QKV_OUT + h * 64) * NTOK;
    const uint32_t* vbase = vbf + (size_t)(b * NHEADS + h) * 32 * (NTOK/2);

    uint32_t sbuf_u32 = (uint32_t)__cvta_generic_to_shared(s_buf);
    int kd = tid >> 4, kc4 = (tid & 15) * 4;
    int vd = tid >> 3, vc4 = (tid & 7) * 4;
    uint32_t k_dst0 = sbuf_u32 + (kd * KSTR2 + kc4) * 4;
    uint32_t v_dst0 = sbuf_u32 + (KBUF2 + vd * VSTR2 + vc4) * 4;
    const float*    k_src0 = base + (16 + kd) * NTOK + kc4;
    const uint32_t* v_src0 = vbase + vd * (NTOK/2) + vc4;

    // q tile (pre-scaled tf32 written by K1): plain copy
    for (int i = tid; i < 16 * 128; i += 256) {
        int d = i >> 7, mm = i & 127;
        s_q[mm * QSTR + d] = base[d * NTOK + m0 + mm];
    }
    __syncthreads();

    uint32_t aq[2][4];
    #pragma unroll
    for (int kk = 0; kk < 2; kk++) {
        aq[kk][0] = __float_as_uint(s_q[(mw + qr)     * QSTR + kk * 8 + qc]);
        aq[kk][1] = __float_as_uint(s_q[(mw + qr + 8) * QSTR + kk * 8 + qc]);
        aq[kk][2] = __float_as_uint(s_q[(mw + qr)     * QSTR + kk * 8 + qc + 4]);
        aq[kk][3] = __float_as_uint(s_q[(mw + qr + 8) * QSTR + kk * 8 + qc + 4]);
    }

    float rs0 = 0.f, rs1 = 0.f;
    float O[4][4];
    #pragma unroll
    for (int i = 0; i < 4; i++)
        #pragma unroll
        for (int j = 0; j < 4; j++) O[i][j] = 0.f;

    CP16(k_dst0, k_src0);
    CP16(v_dst0, v_src0);
    asm volatile("cp.async.commit_group;");

    for (int t = 0; t < 16; t++) {
        asm volatile("cp.async.wait_group 0;");
        __syncthreads();

        if (t < 15) {
            int n0 = (t + 1) * 64;
            uint32_t off = ((t + 1) & 1) * BUFSZ2 * 4;
            CP16(k_dst0 + off, k_src0 + n0);
            CP16(v_dst0 + off, v_src0 + (n0 >> 1));
            asm volatile("cp.async.commit_group;");
        }

        const float*    kf = s_buf + (t & 1) * BUFSZ2;
        const uint32_t* vw = (const uint32_t*)(kf + KBUF2);

        // ---- QK (tf32)
        float S[8][4];
        #pragma unroll
        for (int nt = 0; nt < 8; nt++) {
            float d0 = 0.f, d1 = 0.f, d2 = 0.f, d3 = 0.f;
            #pragma unroll
            for (int kk = 0; kk < 2; kk++) {
                uint32_t b0 = __float_as_uint(kf[(kk*8 + qc)     * KSTR2 + nt*8 + qr]);
                uint32_t b1 = __float_as_uint(kf[(kk*8 + qc + 4) * KSTR2 + nt*8 + qr]);
                mma_tf32(d0, d1, d2, d3,
                         aq[kk][0], aq[kk][1], aq[kk][2], aq[kk][3], b0, b1);
            }
            S[nt][0] = d0; S[nt][1] = d1; S[nt][2] = d2; S[nt][3] = d3;
        }

        // ---- fused exp2 + PV per kt: MUFU bursts overlap tensor work
        float ps0 = 0.f, ps1 = 0.f;
        #pragma unroll
        for (int kt = 0; kt < 4; kt++) {
            float e00 = fex2(S[2*kt][0]);
            float e01 = fex2(S[2*kt][1]);
            float e02 = fex2(S[2*kt][2]);
            float e03 = fex2(S[2*kt][3]);
            float e10 = fex2(S[2*kt+1][0]);
            float e11 = fex2(S[2*kt+1][1]);
            float e12 = fex2(S[2*kt+1][2]);
            float e13 = fex2(S[2*kt+1][3]);
            ps0 += (e00 + e01) + (e10 + e11);
            ps1 += (e02 + e03) + (e12 + e13);
            uint32_t a0 = pk2(e00, e01);
            uint32_t a1 = pk2(e02, e03);
            uint32_t a2 = pk2(e10, e11);
            uint32_t a3 = pk2(e12, e13);
            #pragma unroll
            for (int dt = 0; dt < 4; dt++) {
                uint32_t b0 = vw[(dt*8 + qr) * VSTR2 + kt*8 + qc];
                uint32_t b1 = vw[(dt*8 + qr) * VSTR2 + kt*8 + qc + 4];
                mma_bf16(O[dt][0], O[dt][1], O[dt][2], O[dt][3],
                         a0, a1, a2, a3, b0, b1);
            }
        }
        rs0 += ps0;
        rs1 += ps1;
    }
    __syncthreads();

    rs0 += __shfl_xor_sync(0xffffffffu, rs0, 1);
    rs0 += __shfl_xor_sync(0xffffffffu, rs0, 2);
    rs1 += __shfl_xor_sync(0xffffffffu, rs1, 1);
    rs1 += __shfl_xor_sync(0xffffffffu, rs1, 2);
    float inv0 = 1.0f / rs0, inv1 = 1.0f / rs1;

    float* ob   = s_all;            // [128][33]
    float* pv   = s_all + 4224;     // [32][6][34]
    float* pwb  = s_all + 10752;    // 288
    float* pinv = s_all + 11040;    // 32
    float* psh  = s_all + 11072;    // 32

    #pragma unroll
    for (int dt = 0; dt < 4; dt++) {
        ob[(mw + qr)     * 33 + dt*8 + 2*qc]     = O[dt][0] * inv0;
        ob[(mw + qr)     * 33 + dt*8 + 2*qc + 1] = O[dt][1] * inv0;
        ob[(mw + qr + 8) * 33 + dt*8 + 2*qc]     = O[dt][2] * inv1;
        ob[(mw + qr + 8) * 33 + dt*8 + 2*qc + 1] = O[dt][3] * inv1;
    }

    {
        int r0 = blockIdx.x * 4;
        const float* vfp = base + 32 * NTOK;
        for (int i = tid; i < 32 * 6 * 34; i += 256) {
            int d  = i / 204;
            int rm = i % 204;
            int yy = rm / 34;
            int xx = rm % 34;
            int x  = xx - 1;
            int ry = r0 - 1 + yy;
            float val = 0.f;
            if ((unsigned)x < 32u && (unsigned)ry < 32u)
                val = vfp[d * NTOK + ry * 32 + x];
            pv[i] = val;
        }
        for (int i = tid; i < 288; i += 256)
            pwb[i] = pe_w[h * 32 * 9 + i];
        if (tid < 32) {
            int c = h * 32 + tid;
            float iv = pe_g[c] * rsqrtf(pe_v[c] + BN_EPS);
            pinv[tid] = iv;
            psh[tid]  = pe_b[c] - pe_m[c] * iv;
        }
    }
    __syncthreads();

    // out = tf32( v_attn + BN(dwconv3x3(v)) )  -> K4 consumes cvt-free
    float* outp = vattn + ((size_t)b * DIM + h * HEAD_DIM) * NTOK + m0;
    for (int i = tid; i < 32 * 128; i += 256) {
        int d = i >> 7, mm = i & 127;
        int y = mm >> 5, x = mm & 31;
        const float* wd = &pwb[d * 9];
        const float* p0 = &pv[d * 204 + y * 34 + x];
        float pe = wd[0]*p0[0]  + wd[1]*p0[1]  + wd[2]*p0[2]
                 + wd[3]*p0[34] + wd[4]*p0[35] + wd[5]*p0[36]
                 + wd[6]*p0[68] + wd[7]*p0[69] + wd[8]*p0[70];
        outp[d * NTOK + mm] = tf32r(ob[mm * 33 + d] + pe * pinv[d] + psh[d]);
    }
}

// ---------------------------------------------------------------------------
extern "C" void kernel_launch(void* const* d_in, const int* in_sizes, int n_in,
                              void* d_out, int out_size)
{
    const float* x        = (const float*)d_in[0];
    const float* qkv_w    = (const float*)d_in[1];
    const float* qkv_g    = (const float*)d_in[2];
    const float* qkv_b    = (const float*)d_in[3];
    const float* qkv_m    = (const float*)d_in[4];
    const float* qkv_v    = (const float*)d_in[5];
    const float* pe_w     = (const float*)d_in[6];
    const float* pe_g     = (const float*)d_in[7];
    const float* pe_b     = (const float*)d_in[8];
    const float* pe_m     = (const float*)d_in[9];
    const float* pe_v     = (const float*)d_in[10];
    const float* proj_w   = (const float*)d_in[11];
    const float* proj_g   = (const float*)d_in[12];
    const float* proj_b   = (const float*)d_in[13];
    const float* proj_m   = (const float*)d_in[14];
    const float* proj_v   = (const float*)d_in[15];
    float* out            = (float*)d_out;

    float *qkv_ptr, *vattn_ptr, *xr_ptr, *wq_ptr, *wp_ptr;
    uint32_t* vbf_ptr;
    cudaGetSymbolAddress((void**)&qkv_ptr, g_qkv);
    cudaGetSymbolAddress((void**)&vattn_ptr, g_vattn);
    cudaGetSymbolAddress((void**)&xr_ptr, g_xr);
    cudaGetSymbolAddress((void**)&wq_ptr, g_wq);
    cudaGetSymbolAddress((void**)&wp_ptr, g_wp);
    cudaGetSymbolAddress((void**)&vbf_ptr, g_vbf);

    cudaFuncSetAttribute(gemm_bn_tc,
        cudaFuncAttributeMaxDynamicSharedMemorySize, G_SMEM_BYTES);

    // K0: pre-round inputs to tf32
    prep_kernel<<<512, 256>>>(x, qkv_w, proj_w);

    // K1: qkv = BN(conv1x1(x)) + attn-operand formatting
    gemm_bn_tc<<<dim3(8, 4, BATCH), 512, G_SMEM_BYTES>>>(
        xr_ptr, wq_ptr, qkv_g, qkv_b, qkv_m, qkv_v, qkv_ptr, vbf_ptr, QKV_OUT);

    // K2: attention (max-free softmax, fused exp/PV) + fused pos-enc
    attn_kernel<<<dim3(8, NHEADS, BATCH), 256>>>(
        qkv_ptr, vbf_ptr, vattn_ptr, pe_w, pe_g, pe_b, pe_m, pe_v);

    // K4: out = BN(conv1x1(vattn))
    gemm_bn_tc<<<dim3(8, 2, BATCH), 512, G_SMEM_BYTES>>>(
        vattn_ptr, wp_ptr, proj_g, proj_b, proj_m, proj_v, out, vbf_ptr, DIM);
}